// round 6
// baseline (speedup 1.0000x reference)
#include <cuda_runtime.h>
#include <cuda_bf16.h>

#define B    8
#define C    256
#define HW4  16384                              // float4 per (b,c) plane
#define F4_PER_BLOCK  1024                      // 4 float4/thread * 256 threads
#define BLOCKS_PER_PLANE (HW4 / F4_PER_BLOCK)   // 16
#define GATE_BLOCKS 256

// Scratch (no allocation allowed -> __device__ globals)
__device__ float g_h[B * C];
__device__ float g_logits[B * C];
__device__ float g_scale[B * C];
__device__ unsigned int g_bar1, g_bar2;         // epoch-counting grid barriers

// Epoch-based grid barrier: never reset, monotone across graph replays.
// All arrivals within one launch land in [E*nb, (E+1)*nb); target=(E+1)*nb.
__device__ __forceinline__ void grid_barrier(unsigned int* bar, unsigned int nb) {
    __threadfence();                 // publish this block's global writes
    __syncthreads();
    if (threadIdx.x == 0) {
        unsigned int v = atomicAdd(bar, 1u);
        unsigned int target = (v / nb + 1u) * nb;
        volatile unsigned int* vb = bar;
        while (*vb < target) { }
    }
    __syncthreads();
    __threadfence();                 // acquire: peers' writes now visible
}

// ---------------------------------------------------------------------------
// Fused gate: layer1 -> barrier -> layer2 -> barrier -> softmax (blocks 0..7).
// 256 blocks x 256 threads; warp-per-output coalesced float4 matvecs.
// NO explicit PDL trigger: completion fires at kernel end, so the dependent
// scale kernel's cudaGridDependencySynchronize() sees finished g_scale.
// ---------------------------------------------------------------------------
__global__ void __launch_bounds__(256) gate_kernel(const float* __restrict__ semantic,
                                                   const float* __restrict__ W1,
                                                   const float* __restrict__ b1,
                                                   const float* __restrict__ W2,
                                                   const float* __restrict__ b2) {
    const int tid  = threadIdx.x;
    const int lane = tid & 31;
    const int wg   = blockIdx.x * 8 + (tid >> 5);   // 0..2047
    const int b    = wg >> 8;
    const int c    = wg & 255;

    // -------- Layer 1: g_h = leaky_relu(semantic @ W1^T + b1) --------------
    {
        const float4* __restrict__ w4 = (const float4*)(W1 + c * C);
        const float4* __restrict__ i4 = (const float4*)(semantic + b * C);
        float4 wa = __ldg(w4 + lane), wb = __ldg(w4 + lane + 32);
        float4 ia = __ldg(i4 + lane), ib = __ldg(i4 + lane + 32);
        float p = wa.x*ia.x + wa.y*ia.y + wa.z*ia.z + wa.w*ia.w
                + wb.x*ib.x + wb.y*ib.y + wb.z*ib.z + wb.w*ib.w;
        #pragma unroll
        for (int s = 16; s > 0; s >>= 1) p += __shfl_xor_sync(0xffffffffu, p, s);
        if (lane == 0) {
            float r = p + __ldg(b1 + c);
            g_h[b * C + c] = r > 0.0f ? r : 0.1f * r;
        }
    }
    grid_barrier(&g_bar1, GATE_BLOCKS);

    // -------- Layer 2: g_logits = g_h @ W2^T + b2 --------------------------
    {
        const float4* __restrict__ w4 = (const float4*)(W2 + c * C);
        const float4* __restrict__ i4 = (const float4*)(g_h + b * C);
        float4 wa = __ldg(w4 + lane), wb = __ldg(w4 + lane + 32);
        float4 ia = i4[lane], ib = i4[lane + 32];
        float p = wa.x*ia.x + wa.y*ia.y + wa.z*ia.z + wa.w*ia.w
                + wb.x*ib.x + wb.y*ib.y + wb.z*ib.z + wb.w*ib.w;
        #pragma unroll
        for (int s = 16; s > 0; s >>= 1) p += __shfl_xor_sync(0xffffffffu, p, s);
        if (lane == 0) g_logits[b * C + c] = p + __ldg(b2 + c);
    }
    grid_barrier(&g_bar2, GATE_BLOCKS);

    // -------- Softmax: block bb handles batch row bb -----------------------
    if (blockIdx.x < B) {
        const int bb = blockIdx.x;
        __shared__ float red[C];
        const float logit = g_logits[bb * C + tid];
        red[tid] = logit;
        __syncthreads();
        #pragma unroll
        for (int s = 128; s > 0; s >>= 1) {
            if (tid < s) red[tid] = fmaxf(red[tid], red[tid + s]);
            __syncthreads();
        }
        const float m = red[0];
        __syncthreads();
        const float e = __expf(logit - m);
        red[tid] = e;
        __syncthreads();
        #pragma unroll
        for (int s = 128; s > 0; s >>= 1) {
            if (tid < s) red[tid] += red[tid + s];
            __syncthreads();
        }
        g_scale[bb * C + tid] = 1.0f + e / red[0];
    }
}

// ---------------------------------------------------------------------------
// y = x * scale[plane]. Prefetch x BEFORE the PDL dependency sync so the
// stream's first reads overlap the gate kernel; only the g_scale read waits
// (for FULL gate completion — no early trigger this time).
// ---------------------------------------------------------------------------
__global__ void __launch_bounds__(256) scale_kernel(const float4* __restrict__ x,
                                                    float4* __restrict__ y) {
    const int blk   = blockIdx.x;
    const size_t i0 = (size_t)blk * F4_PER_BLOCK + threadIdx.x;

    float4 v0 = __ldcs(x + i0);
    float4 v1 = __ldcs(x + i0 + 256);
    float4 v2 = __ldcs(x + i0 + 512);
    float4 v3 = __ldcs(x + i0 + 768);

#if __CUDA_ARCH__ >= 900
    cudaGridDependencySynchronize();
#endif
    const float s = __ldg(&g_scale[blk >> 4]);

    v0.x *= s; v0.y *= s; v0.z *= s; v0.w *= s;
    v1.x *= s; v1.y *= s; v1.z *= s; v1.w *= s;
    v2.x *= s; v2.y *= s; v2.z *= s; v2.w *= s;
    v3.x *= s; v3.y *= s; v3.z *= s; v3.w *= s;

    __stcs(y + i0,       v0);
    __stcs(y + i0 + 256, v1);
    __stcs(y + i0 + 512, v2);
    __stcs(y + i0 + 768, v3);
}

extern "C" void kernel_launch(void* const* d_in, const int* in_sizes, int n_in,
                              void* d_out, int out_size) {
    const float* x        = (const float*)d_in[0];
    const float* semantic = (const float*)d_in[1];
    const float* W1       = (const float*)d_in[2];
    const float* b1       = (const float*)d_in[3];
    const float* W2       = (const float*)d_in[4];
    const float* b2       = (const float*)d_in[5];
    float* out = (float*)d_out;

    gate_kernel<<<GATE_BLOCKS, 256>>>(semantic, W1, b1, W2, b2);

    // PDL: scale kernel may spin up while gate_kernel runs (prefetching x);
    // cudaGridDependencySynchronize() inside waits for gate_kernel to FINISH
    // before g_scale is read (no early trigger in the gate).
    cudaLaunchConfig_t cfg = {};
    cfg.gridDim  = dim3((B * C) * BLOCKS_PER_PLANE, 1, 1);   // 32768
    cfg.blockDim = dim3(256, 1, 1);
    cfg.dynamicSmemBytes = 0;
    cfg.stream = 0;
    cudaLaunchAttribute attr[1];
    attr[0].id = cudaLaunchAttributeProgrammaticStreamSerialization;
    attr[0].val.programmaticStreamSerializationAllowed = 1;
    cfg.attrs = attr;
    cfg.numAttrs = 1;
    cudaLaunchKernelEx(&cfg, scale_kernel, (const float4*)x, (float4*)out);
}